// round 1
// baseline (speedup 1.0000x reference)
#include <cuda_runtime.h>
#include <math.h>

#define EMBED 2048
#define DFF   8192
#define MROWS 4096   // B*N
#define SEQ   2048
#define NH    16
#define HD    128
#define LN_EPS 1e-5f

// ---------------- scratch (device globals; no allocation allowed) ----------
__device__ float g_q[MROWS * EMBED];
__device__ float g_k[MROWS * EMBED];
__device__ float g_v[MROWS * EMBED];
__device__ float g_attn[MROWS * EMBED];
__device__ float g_tmp[MROWS * EMBED];
__device__ float g_h[MROWS * EMBED];
__device__ float g_ff[MROWS * DFF];

// ---------------- SGEMM: C = A @ B + bias (optional GELU) ------------------
// A [M,K] row-major, B [K,N] row-major, C [M,N]. M%128==0, N%128==0, K%16==0.
#define BM 128
#define BN 128
#define BK 16
#define TM 8
#define TN 8

__device__ __forceinline__ float gelu_exact(float x) {
    return 0.5f * x * (1.0f + erff(x * 0.70710678118654752f));
}

template <int EPI>  // 0 = bias only, 1 = bias + gelu
__global__ __launch_bounds__(256, 2)
void gemm_kernel(const float* __restrict__ A, const float* __restrict__ B,
                 const float* __restrict__ bias, float* __restrict__ C,
                 int M, int N, int K) {
    __shared__ float As[BK][BM];
    __shared__ float Bs[BK][BN];

    const int bx = blockIdx.x;   // along N
    const int by = blockIdx.y;   // along M
    const int tid = threadIdx.x; // 256
    const int tx = tid & 15;
    const int ty = tid >> 4;

    const float* Aptr = A + (size_t)by * BM * K;
    const float* Bptr = B + (size_t)bx * BN;

    // A tile: 128 rows x 16 cols = 512 float4, 2 per thread
    const int aRow = tid >> 2;         // 0..63 (+64 second pass)
    const int aCol = (tid & 3) * 4;    // 0,4,8,12
    // B tile: 16 rows x 128 cols = 512 float4, 2 per thread
    const int bRow = tid >> 5;         // 0..7 (+8 second pass)
    const int bCol = (tid & 31) * 4;   // 0..124

    float acc[TM][TN];
#pragma unroll
    for (int i = 0; i < TM; i++)
#pragma unroll
        for (int j = 0; j < TN; j++) acc[i][j] = 0.f;

    for (int k0 = 0; k0 < K; k0 += BK) {
#pragma unroll
        for (int p = 0; p < 2; p++) {
            int r = aRow + p * 64;
            float4 va = *(const float4*)(Aptr + (size_t)r * K + k0 + aCol);
            As[aCol + 0][r] = va.x;
            As[aCol + 1][r] = va.y;
            As[aCol + 2][r] = va.z;
            As[aCol + 3][r] = va.w;
        }
#pragma unroll
        for (int p = 0; p < 2; p++) {
            int r = bRow + p * 8;
            *(float4*)(&Bs[r][bCol]) = *(const float4*)(Bptr + (size_t)(k0 + r) * N + bCol);
        }
        __syncthreads();

#pragma unroll
        for (int k = 0; k < BK; k++) {
            float4 a0 = *(const float4*)(&As[k][ty * TM]);
            float4 a1 = *(const float4*)(&As[k][ty * TM + 4]);
            float4 b0 = *(const float4*)(&Bs[k][tx * TN]);
            float4 b1 = *(const float4*)(&Bs[k][tx * TN + 4]);
            float ar[TM] = {a0.x, a0.y, a0.z, a0.w, a1.x, a1.y, a1.z, a1.w};
            float br[TN] = {b0.x, b0.y, b0.z, b0.w, b1.x, b1.y, b1.z, b1.w};
#pragma unroll
            for (int i = 0; i < TM; i++)
#pragma unroll
                for (int j = 0; j < TN; j++) acc[i][j] += ar[i] * br[j];
        }
        __syncthreads();
    }

#pragma unroll
    for (int i = 0; i < TM; i++) {
        int row = by * BM + ty * TM + i;
#pragma unroll
        for (int j = 0; j < TN; j += 4) {
            int col = bx * BN + tx * TN + j;
            float4 v;
            v.x = acc[i][j + 0] + bias[col + 0];
            v.y = acc[i][j + 1] + bias[col + 1];
            v.z = acc[i][j + 2] + bias[col + 2];
            v.w = acc[i][j + 3] + bias[col + 3];
            if (EPI == 1) {
                v.x = gelu_exact(v.x);
                v.y = gelu_exact(v.y);
                v.z = gelu_exact(v.z);
                v.w = gelu_exact(v.w);
            }
            *(float4*)(C + (size_t)row * N + col) = v;
        }
    }
}

// ---------------- flash attention (fp32, online softmax) -------------------
// Q,K,V laid out [B, N, C] with head h at columns [h*128, h*128+128).
#define QT 64
#define KT 32
#define QS 129   // padded row stride for Q/K/V tiles
#define SS 33    // padded row stride for score tile
#define ATTN_SMEM_FLOATS (QT * QS + KT * QS + KT * QS + QT * SS + 3 * QT)

__global__ __launch_bounds__(256, 2)
void attn_kernel(const float* __restrict__ Q, const float* __restrict__ K,
                 const float* __restrict__ V, float* __restrict__ O) {
    extern __shared__ float sm[];
    float* Qs  = sm;
    float* Ks  = Qs + QT * QS;
    float* Vs  = Ks + KT * QS;
    float* Ssh = Vs + KT * QS;
    float* m_s = Ssh + QT * SS;
    float* l_s = m_s + QT;
    float* fac = l_s + QT;

    const int tid = threadIdx.x;
    const int qt  = blockIdx.x;          // query tile
    const int bh  = blockIdx.y;          // b*NH + h
    const int b = bh / NH, h = bh % NH;

    const float* Qg = Q + ((size_t)b * SEQ) * EMBED + h * HD;
    const float* Kg = K + ((size_t)b * SEQ) * EMBED + h * HD;
    const float* Vg = V + ((size_t)b * SEQ) * EMBED + h * HD;
    float*       Og = O + ((size_t)b * SEQ) * EMBED + h * HD;

    const float scale = 0.08838834764831845f;  // 1/sqrt(128)

    // load Q tile (scaled): 64x128 = 2048 float4, 8 per thread
#pragma unroll
    for (int i = 0; i < 8; i++) {
        int lin = tid + i * 256;
        int r = lin >> 5;          // /32
        int c4 = lin & 31;
        float4 v = *(const float4*)(Qg + (size_t)(qt * QT + r) * EMBED + c4 * 4);
        Qs[r * QS + c4 * 4 + 0] = v.x * scale;
        Qs[r * QS + c4 * 4 + 1] = v.y * scale;
        Qs[r * QS + c4 * 4 + 2] = v.z * scale;
        Qs[r * QS + c4 * 4 + 3] = v.w * scale;
    }
    if (tid < QT) { m_s[tid] = -1e30f; l_s[tid] = 0.f; }

    const int qg = tid >> 3;      // 0..31 -> 2 query rows each
    const int kg = tid & 7;       // 0..7  -> 4 keys each (S phase)
    const int dg = tid & 7;       // 0..7  -> dims d = dg + 8*i (O phase)
    const int q0 = qg * 2, q1 = q0 + 1;

    float o0[16], o1[16];
#pragma unroll
    for (int i = 0; i < 16; i++) { o0[i] = 0.f; o1[i] = 0.f; }

    __syncthreads();

    for (int t = 0; t < SEQ / KT; t++) {
        // load K,V tiles: 32x128 = 1024 float4 each, 4 per thread
#pragma unroll
        for (int i = 0; i < 4; i++) {
            int lin = tid + i * 256;
            int r = lin >> 5;
            int c4 = lin & 31;
            size_t goff = (size_t)(t * KT + r) * EMBED + c4 * 4;
            float4 kv = *(const float4*)(Kg + goff);
            Ks[r * QS + c4 * 4 + 0] = kv.x;
            Ks[r * QS + c4 * 4 + 1] = kv.y;
            Ks[r * QS + c4 * 4 + 2] = kv.z;
            Ks[r * QS + c4 * 4 + 3] = kv.w;
            float4 vv = *(const float4*)(Vg + goff);
            Vs[r * QS + c4 * 4 + 0] = vv.x;
            Vs[r * QS + c4 * 4 + 1] = vv.y;
            Vs[r * QS + c4 * 4 + 2] = vv.z;
            Vs[r * QS + c4 * 4 + 3] = vv.w;
        }
        __syncthreads();

        // S = Q K^T  (each thread: 2 queries x 4 keys)
        float s0[4] = {0, 0, 0, 0}, s1[4] = {0, 0, 0, 0};
#pragma unroll 8
        for (int d = 0; d < HD; d++) {
            float a0 = Qs[q0 * QS + d];
            float a1 = Qs[q1 * QS + d];
#pragma unroll
            for (int j = 0; j < 4; j++) {
                float kv = Ks[(kg * 4 + j) * QS + d];
                s0[j] += a0 * kv;
                s1[j] += a1 * kv;
            }
        }
#pragma unroll
        for (int j = 0; j < 4; j++) {
            Ssh[q0 * SS + kg * 4 + j] = s0[j];
            Ssh[q1 * SS + kg * 4 + j] = s1[j];
        }
        __syncthreads();

        // online softmax row update (one thread per query row)
        if (tid < QT) {
            int r = tid;
            float mold = m_s[r];
            float mx = mold;
#pragma unroll
            for (int k2 = 0; k2 < KT; k2++) mx = fmaxf(mx, Ssh[r * SS + k2]);
            float f = __expf(mold - mx);
            float sum = 0.f;
#pragma unroll
            for (int k2 = 0; k2 < KT; k2++) {
                float p = __expf(Ssh[r * SS + k2] - mx);
                Ssh[r * SS + k2] = p;
                sum += p;
            }
            l_s[r] = l_s[r] * f + sum;
            m_s[r] = mx;
            fac[r] = f;
        }
        __syncthreads();

        // O += P V  (each thread: 2 queries x 16 dims, d = dg + 8*i)
        float f0 = fac[q0], f1 = fac[q1];
#pragma unroll
        for (int i = 0; i < 16; i++) { o0[i] *= f0; o1[i] *= f1; }
        for (int k2 = 0; k2 < KT; k2++) {
            float p0 = Ssh[q0 * SS + k2];
            float p1 = Ssh[q1 * SS + k2];
#pragma unroll
            for (int i = 0; i < 16; i++) {
                float vv = Vs[k2 * QS + dg + 8 * i];
                o0[i] += p0 * vv;
                o1[i] += p1 * vv;
            }
        }
        __syncthreads();
    }

    float inv0 = 1.f / l_s[q0];
    float inv1 = 1.f / l_s[q1];
#pragma unroll
    for (int i = 0; i < 16; i++) {
        Og[(size_t)(qt * QT + q0) * EMBED + dg + 8 * i] = o0[i] * inv0;
        Og[(size_t)(qt * QT + q1) * EMBED + dg + 8 * i] = o1[i] * inv1;
    }
}

// ---------------- residual + layernorm -------------------------------------
// out[r,:] = LN(A[r,:] + C[r,:]) * g + b, row length EMBED, block per row.
__global__ __launch_bounds__(256)
void add_ln_kernel(const float* __restrict__ A, const float* __restrict__ Cv,
                   const float* __restrict__ g, const float* __restrict__ be,
                   float* __restrict__ out) {
    const int r = blockIdx.x;
    const int tid = threadIdx.x;
    __shared__ float red[8];
    __shared__ float bcast;

    float v[8];
    float sum = 0.f;
#pragma unroll
    for (int i = 0; i < 8; i++) {
        int idx = tid + i * 256;
        v[i] = A[(size_t)r * EMBED + idx] + Cv[(size_t)r * EMBED + idx];
        sum += v[i];
    }
#pragma unroll
    for (int o = 16; o > 0; o >>= 1) sum += __shfl_xor_sync(0xffffffff, sum, o);
    if ((tid & 31) == 0) red[tid >> 5] = sum;
    __syncthreads();
    if (tid == 0) {
        float s = 0.f;
#pragma unroll
        for (int i = 0; i < 8; i++) s += red[i];
        bcast = s;
    }
    __syncthreads();
    float mu = bcast * (1.0f / EMBED);

    float var = 0.f;
#pragma unroll
    for (int i = 0; i < 8; i++) {
        float d = v[i] - mu;
        var += d * d;
    }
#pragma unroll
    for (int o = 16; o > 0; o >>= 1) var += __shfl_xor_sync(0xffffffff, var, o);
    if ((tid & 31) == 0) red[tid >> 5] = var;
    __syncthreads();
    if (tid == 0) {
        float s = 0.f;
#pragma unroll
        for (int i = 0; i < 8; i++) s += red[i];
        bcast = s;
    }
    __syncthreads();
    float inv = rsqrtf(bcast * (1.0f / EMBED) + LN_EPS);

#pragma unroll
    for (int i = 0; i < 8; i++) {
        int idx = tid + i * 256;
        out[(size_t)r * EMBED + idx] = (v[i] - mu) * inv * g[idx] + be[idx];
    }
}

// ---------------- launch ----------------------------------------------------
extern "C" void kernel_launch(void* const* d_in, const int* in_sizes, int n_in,
                              void* d_out, int out_size) {
    const float* x  = (const float*)d_in[0];
    const float* Wq = (const float*)d_in[1];
    const float* bq = (const float*)d_in[2];
    const float* Wk = (const float*)d_in[3];
    const float* bk = (const float*)d_in[4];
    const float* Wv = (const float*)d_in[5];
    const float* bv = (const float*)d_in[6];
    const float* Wo = (const float*)d_in[7];
    const float* bo = (const float*)d_in[8];
    const float* g1 = (const float*)d_in[9];
    const float* b1 = (const float*)d_in[10];
    const float* g2 = (const float*)d_in[11];
    const float* b2 = (const float*)d_in[12];
    const float* W1  = (const float*)d_in[13];
    const float* bf1 = (const float*)d_in[14];
    const float* W2  = (const float*)d_in[15];
    const float* bf2 = (const float*)d_in[16];
    float* out = (float*)d_out;

    float *q, *k, *v, *attn, *tmp, *h, *ff;
    cudaGetSymbolAddress((void**)&q, g_q);
    cudaGetSymbolAddress((void**)&k, g_k);
    cudaGetSymbolAddress((void**)&v, g_v);
    cudaGetSymbolAddress((void**)&attn, g_attn);
    cudaGetSymbolAddress((void**)&tmp, g_tmp);
    cudaGetSymbolAddress((void**)&h, g_h);
    cudaGetSymbolAddress((void**)&ff, g_ff);

    const int attn_smem = ATTN_SMEM_FLOATS * sizeof(float);
    cudaFuncSetAttribute(attn_kernel, cudaFuncAttributeMaxDynamicSharedMemorySize, attn_smem);

    dim3 blk(256);
    dim3 grid_proj(EMBED / BN, MROWS / BM);   // (16, 32)
    dim3 grid_ff1(DFF / BN, MROWS / BM);      // (64, 32)

    // QKV projections
    gemm_kernel<0><<<grid_proj, blk>>>(x, Wq, bq, q, MROWS, EMBED, EMBED);
    gemm_kernel<0><<<grid_proj, blk>>>(x, Wk, bk, k, MROWS, EMBED, EMBED);
    gemm_kernel<0><<<grid_proj, blk>>>(x, Wv, bv, v, MROWS, EMBED, EMBED);

    // attention
    attn_kernel<<<dim3(SEQ / QT, 2 * NH), blk, attn_smem>>>(q, k, v, attn);

    // output projection, residual + LN1
    gemm_kernel<0><<<grid_proj, blk>>>(attn, Wo, bo, tmp, MROWS, EMBED, EMBED);
    add_ln_kernel<<<MROWS, blk>>>(x, tmp, g1, b1, h);

    // FFN
    gemm_kernel<1><<<grid_ff1, blk>>>(h, W1, bf1, ff, MROWS, DFF, EMBED);
    gemm_kernel<0><<<grid_proj, blk>>>(ff, W2, bf2, tmp, MROWS, EMBED, DFF);

    // residual + LN2 -> output
    add_ln_kernel<<<MROWS, blk>>>(h, tmp, g2, b2, out);
}

// round 4
// speedup vs baseline: 1.8646x; 1.8646x over previous
#include <cuda_runtime.h>
#include <cuda_bf16.h>
#include <math.h>

#define EMBED 2048
#define DFF   8192
#define MROWS 4096   // B*N
#define SEQ   2048
#define NH    16
#define HD    128
#define LN_EPS 1e-5f

// ---------------- scratch (device globals; no allocation allowed) ----------
__device__ float g_q[MROWS * EMBED];
__device__ float g_k[MROWS * EMBED];
__device__ float g_v[MROWS * EMBED];
__device__ float g_attn[MROWS * EMBED];
__device__ float g_tmp[MROWS * EMBED];
__device__ float g_h[MROWS * EMBED];
__device__ float g_ff[MROWS * DFF];

// split+transposed weights [N,K] bf16 (hi/lo)
__device__ __nv_bfloat16 g_wq_hi[EMBED * EMBED];
__device__ __nv_bfloat16 g_wq_lo[EMBED * EMBED];
__device__ __nv_bfloat16 g_wk_hi[EMBED * EMBED];
__device__ __nv_bfloat16 g_wk_lo[EMBED * EMBED];
__device__ __nv_bfloat16 g_wv_hi[EMBED * EMBED];
__device__ __nv_bfloat16 g_wv_lo[EMBED * EMBED];
__device__ __nv_bfloat16 g_wo_hi[EMBED * EMBED];
__device__ __nv_bfloat16 g_wo_lo[EMBED * EMBED];
__device__ __nv_bfloat16 g_w1_hi[EMBED * DFF];
__device__ __nv_bfloat16 g_w1_lo[EMBED * DFF];
__device__ __nv_bfloat16 g_w2_hi[DFF * EMBED];
__device__ __nv_bfloat16 g_w2_lo[DFF * EMBED];

// ---------------- weight prep: W[K,N] fp32 -> Wt[N,K] bf16 hi/lo -----------
__global__ __launch_bounds__(256)
void split_transpose_kernel(const float* __restrict__ W,
                            __nv_bfloat16* __restrict__ hi,
                            __nv_bfloat16* __restrict__ lo,
                            int K, int N) {
    __shared__ float t[32][33];
    const int k0 = blockIdx.x * 32;
    const int n0 = blockIdx.y * 32;
    const int tid = threadIdx.x;
#pragma unroll
    for (int i = 0; i < 4; i++) {
        int lin = i * 256 + tid;
        int r = lin >> 5, c = lin & 31;       // r = k offset, c = n offset
        t[r][c] = W[(size_t)(k0 + r) * N + n0 + c];
    }
    __syncthreads();
#pragma unroll
    for (int i = 0; i < 4; i++) {
        int lin = i * 256 + tid;
        int n = lin >> 5, k = lin & 31;
        float x = t[k][n];
        __nv_bfloat16 h = __float2bfloat16(x);
        __nv_bfloat16 l = __float2bfloat16(x - __bfloat162float(h));
        size_t off = (size_t)(n0 + n) * K + k0 + k;
        hi[off] = h;
        lo[off] = l;
    }
}

// ---------------- tensor-core GEMM (bf16x3 split precision) ----------------
// C[M,N] = A[M,K](fp32) @ W[K,N] + bias, using Wt hi/lo in [N,K] bf16.
#define SAST 40  // padded smem row stride (bf16 elems): 80B = 20 b32 banks

__device__ __forceinline__ void mma_bf16(float* c, const unsigned* a,
                                         unsigned b0, unsigned b1) {
    asm volatile(
        "mma.sync.aligned.m16n8k16.row.col.f32.bf16.bf16.f32 "
        "{%0,%1,%2,%3},{%4,%5,%6,%7},{%8,%9},{%0,%1,%2,%3};\n"
        : "+f"(c[0]), "+f"(c[1]), "+f"(c[2]), "+f"(c[3])
        : "r"(a[0]), "r"(a[1]), "r"(a[2]), "r"(a[3]), "r"(b0), "r"(b1));
}

__device__ __forceinline__ void ldsm4(unsigned* r, const __nv_bfloat16* p) {
    unsigned addr = (unsigned)__cvta_generic_to_shared(p);
    asm volatile("ldmatrix.sync.aligned.m8n8.x4.shared.b16 {%0,%1,%2,%3}, [%4];"
                 : "=r"(r[0]), "=r"(r[1]), "=r"(r[2]), "=r"(r[3])
                 : "r"(addr));
}

__device__ __forceinline__ float gelu_exact(float x) {
    return 0.5f * x * (1.0f + erff(x * 0.70710678118654752f));
}

template <int EPI>  // 0 = bias only, 1 = bias + gelu
__global__ __launch_bounds__(256)
void gemm_tc_kernel(const float* __restrict__ A,
                    const __nv_bfloat16* __restrict__ Bhi,
                    const __nv_bfloat16* __restrict__ Blo,
                    const float* __restrict__ bias,
                    float* __restrict__ C, int M, int N, int K) {
    __shared__ __align__(16) __nv_bfloat16 Ash[128 * SAST];
    __shared__ __align__(16) __nv_bfloat16 Asl[128 * SAST];
    __shared__ __align__(16) __nv_bfloat16 Bsh[128 * SAST];
    __shared__ __align__(16) __nv_bfloat16 Bsl[128 * SAST];

    const int tid = threadIdx.x;
    const int lane = tid & 31;
    const int warp = tid >> 5;
    const int wm = (warp & 1) * 64;   // warp tile 64 (M) x 32 (N)
    const int wn = (warp >> 1) * 32;
    const int bx = blockIdx.x, by = blockIdx.y;

    float acc[4][4][4];
#pragma unroll
    for (int i = 0; i < 4; i++)
#pragma unroll
        for (int j = 0; j < 4; j++)
#pragma unroll
            for (int p = 0; p < 4; p++) acc[i][j][p] = 0.f;

    const float* Ap = A + (size_t)(by * 128) * K;
    const __nv_bfloat16* Bhp = Bhi + (size_t)(bx * 128) * K;
    const __nv_bfloat16* Blp = Blo + (size_t)(bx * 128) * K;

    for (int k0 = 0; k0 < K; k0 += 32) {
        // A tile 128x32 fp32 -> split into hi/lo bf16 smem
#pragma unroll
        for (int i = 0; i < 4; i++) {
            int lin = i * 256 + tid;
            int r = lin >> 3, c4 = lin & 7;
            float4 v = *(const float4*)(Ap + (size_t)r * K + k0 + c4 * 4);
            __nv_bfloat162 h01 = __floats2bfloat162_rn(v.x, v.y);
            __nv_bfloat162 h23 = __floats2bfloat162_rn(v.z, v.w);
            __nv_bfloat162 l01 = __floats2bfloat162_rn(
                v.x - __bfloat162float(h01.x), v.y - __bfloat162float(h01.y));
            __nv_bfloat162 l23 = __floats2bfloat162_rn(
                v.z - __bfloat162float(h23.x), v.w - __bfloat162float(h23.y));
            int so = r * SAST + c4 * 4;
            *(__nv_bfloat162*)(&Ash[so]) = h01;
            *(__nv_bfloat162*)(&Ash[so + 2]) = h23;
            *(__nv_bfloat162*)(&Asl[so]) = l01;
            *(__nv_bfloat162*)(&Asl[so + 2]) = l23;
        }
        // B tile: copy 128(n) x 32(k) bf16 hi/lo (coalesced rows of K)
#pragma unroll
        for (int i = 0; i < 2; i++) {
            int lin = i * 256 + tid;
            int n = lin >> 2, kq = lin & 3;
            size_t go = (size_t)n * K + k0 + kq * 8;
            int so = n * SAST + kq * 8;
            *(uint4*)(&Bsh[so]) = *(const uint4*)(Bhp + go);
            *(uint4*)(&Bsl[so]) = *(const uint4*)(Blp + go);
        }
        __syncthreads();

#pragma unroll
        for (int kk = 0; kk < 32; kk += 16) {
            // B fragments: 4 ntiles (8 cols each), hi + lo
            unsigned bh[8], bl[8];
#pragma unroll
            for (int p = 0; p < 2; p++) {
                int nrow = wn + p * 16 + (lane & 7) + ((lane >> 4) << 3);
                int kcol = kk + ((lane >> 3) & 1) * 8;
                ldsm4(&bh[p * 4], &Bsh[nrow * SAST + kcol]);
                ldsm4(&bl[p * 4], &Bsl[nrow * SAST + kcol]);
            }
#pragma unroll
            for (int mt = 0; mt < 4; mt++) {
                int arow = wm + mt * 16 + (lane & 15);
                int acol = kk + ((lane >> 4) << 3);
                unsigned ah[4], al[4];
                ldsm4(ah, &Ash[arow * SAST + acol]);
                ldsm4(al, &Asl[arow * SAST + acol]);
#pragma unroll
                for (int nt = 0; nt < 4; nt++) {
                    mma_bf16(acc[mt][nt], ah, bh[nt * 2], bh[nt * 2 + 1]);
                    mma_bf16(acc[mt][nt], al, bh[nt * 2], bh[nt * 2 + 1]);
                    mma_bf16(acc[mt][nt], ah, bl[nt * 2], bl[nt * 2 + 1]);
                }
            }
        }
        __syncthreads();
    }

    // epilogue: bias (+gelu), fp32 stores
#pragma unroll
    for (int mt = 0; mt < 4; mt++) {
#pragma unroll
        for (int nt = 0; nt < 4; nt++) {
            int row = by * 128 + wm + mt * 16 + (lane >> 2);
            int col = bx * 128 + wn + nt * 8 + (lane & 3) * 2;
            float2 bv = *(const float2*)(bias + col);
            float2 v0, v1;
            v0.x = acc[mt][nt][0] + bv.x;
            v0.y = acc[mt][nt][1] + bv.y;
            v1.x = acc[mt][nt][2] + bv.x;
            v1.y = acc[mt][nt][3] + bv.y;
            if (EPI == 1) {
                v0.x = gelu_exact(v0.x); v0.y = gelu_exact(v0.y);
                v1.x = gelu_exact(v1.x); v1.y = gelu_exact(v1.y);
            }
            *(float2*)(C + (size_t)row * N + col) = v0;
            *(float2*)(C + (size_t)(row + 8) * N + col) = v1;
        }
    }
}

// ---------------- flash attention (fp32, online softmax) -------------------
#define QT 64
#define KT 32
#define QS 129
#define SS 33
#define ATTN_SMEM_FLOATS (QT * QS + KT * QS + KT * QS + QT * SS + 3 * QT)

__global__ __launch_bounds__(256, 2)
void attn_kernel(const float* __restrict__ Q, const float* __restrict__ K,
                 const float* __restrict__ V, float* __restrict__ O) {
    extern __shared__ float sm[];
    float* Qs  = sm;
    float* Ks  = Qs + QT * QS;
    float* Vs  = Ks + KT * QS;
    float* Ssh = Vs + KT * QS;
    float* m_s = Ssh + QT * SS;
    float* l_s = m_s + QT;
    float* fac = l_s + QT;

    const int tid = threadIdx.x;
    const int qt  = blockIdx.x;
    const int bh  = blockIdx.y;
    const int b = bh / NH, h = bh % NH;

    const float* Qg = Q + ((size_t)b * SEQ) * EMBED + h * HD;
    const float* Kg = K + ((size_t)b * SEQ) * EMBED + h * HD;
    const float* Vg = V + ((size_t)b * SEQ) * EMBED + h * HD;
    float*       Og = O + ((size_t)b * SEQ) * EMBED + h * HD;

    const float scale = 0.08838834764831845f;

#pragma unroll
    for (int i = 0; i < 8; i++) {
        int lin = tid + i * 256;
        int r = lin >> 5;
        int c4 = lin & 31;
        float4 v = *(const float4*)(Qg + (size_t)(qt * QT + r) * EMBED + c4 * 4);
        Qs[r * QS + c4 * 4 + 0] = v.x * scale;
        Qs[r * QS + c4 * 4 + 1] = v.y * scale;
        Qs[r * QS + c4 * 4 + 2] = v.z * scale;
        Qs[r * QS + c4 * 4 + 3] = v.w * scale;
    }
    if (tid < QT) { m_s[tid] = -1e30f; l_s[tid] = 0.f; }

    const int qg = tid >> 3;
    const int kg = tid & 7;
    const int dg = tid & 7;
    const int q0 = qg * 2, q1 = q0 + 1;

    float o0[16], o1[16];
#pragma unroll
    for (int i = 0; i < 16; i++) { o0[i] = 0.f; o1[i] = 0.f; }

    __syncthreads();

    for (int t = 0; t < SEQ / KT; t++) {
#pragma unroll
        for (int i = 0; i < 4; i++) {
            int lin = tid + i * 256;
            int r = lin >> 5;
            int c4 = lin & 31;
            size_t goff = (size_t)(t * KT + r) * EMBED + c4 * 4;
            float4 kv = *(const float4*)(Kg + goff);
            Ks[r * QS + c4 * 4 + 0] = kv.x;
            Ks[r * QS + c4 * 4 + 1] = kv.y;
            Ks[r * QS + c4 * 4 + 2] = kv.z;
            Ks[r * QS + c4 * 4 + 3] = kv.w;
            float4 vv = *(const float4*)(Vg + goff);
            Vs[r * QS + c4 * 4 + 0] = vv.x;
            Vs[r * QS + c4 * 4 + 1] = vv.y;
            Vs[r * QS + c4 * 4 + 2] = vv.z;
            Vs[r * QS + c4 * 4 + 3] = vv.w;
        }
        __syncthreads();

        float s0[4] = {0, 0, 0, 0}, s1[4] = {0, 0, 0, 0};
#pragma unroll 8
        for (int d = 0; d < HD; d++) {
            float a0 = Qs[q0 * QS + d];
            float a1 = Qs[q1 * QS + d];
#pragma unroll
            for (int j = 0; j < 4; j++) {
                float kv = Ks[(kg * 4 + j) * QS + d];
                s0[j] += a0 * kv;
                s1[j] += a1 * kv;
            }
        }
#pragma unroll
        for (int j = 0; j < 4; j++) {
            Ssh[q0 * SS + kg * 4 + j] = s0[j];
            Ssh[q1 * SS + kg * 4 + j] = s1[j];
        }
        __syncthreads();

        if (tid < QT) {
            int r = tid;
            float mold = m_s[r];
            float mx = mold;
#pragma unroll
            for (int k2 = 0; k2 < KT; k2++) mx = fmaxf(mx, Ssh[r * SS + k2]);
            float f = __expf(mold - mx);
            float sum = 0.f;
#pragma unroll
            for (int k2 = 0; k2 < KT; k2++) {
                float p = __expf(Ssh[r * SS + k2] - mx);
                Ssh[r * SS + k2] = p;
                sum += p;
            }
            l_s[r] = l_s[r] * f + sum;
            m_s[r] = mx;
            fac[r] = f;
        }
        __syncthreads();

        float f0 = fac[q0], f1 = fac[q1];
#pragma unroll
        for (int i = 0; i < 16; i++) { o0[i] *= f0; o1[i] *= f1; }
        for (int k2 = 0; k2 < KT; k2++) {
            float p0 = Ssh[q0 * SS + k2];
            float p1 = Ssh[q1 * SS + k2];
#pragma unroll
            for (int i = 0; i < 16; i++) {
                float vv = Vs[k2 * QS + dg + 8 * i];
                o0[i] += p0 * vv;
                o1[i] += p1 * vv;
            }
        }
        __syncthreads();
    }

    float inv0 = 1.f / l_s[q0];
    float inv1 = 1.f / l_s[q1];
#pragma unroll
    for (int i = 0; i < 16; i++) {
        Og[(size_t)(qt * QT + q0) * EMBED + dg + 8 * i] = o0[i] * inv0;
        Og[(size_t)(qt * QT + q1) * EMBED + dg + 8 * i] = o1[i] * inv1;
    }
}

// ---------------- residual + layernorm -------------------------------------
__global__ __launch_bounds__(256)
void add_ln_kernel(const float* __restrict__ A, const float* __restrict__ Cv,
                   const float* __restrict__ g, const float* __restrict__ be,
                   float* __restrict__ out) {
    const int r = blockIdx.x;
    const int tid = threadIdx.x;
    __shared__ float red[8];
    __shared__ float bcast;

    float v[8];
    float sum = 0.f;
#pragma unroll
    for (int i = 0; i < 8; i++) {
        int idx = tid + i * 256;
        v[i] = A[(size_t)r * EMBED + idx] + Cv[(size_t)r * EMBED + idx];
        sum += v[i];
    }
#pragma unroll
    for (int o = 16; o > 0; o >>= 1) sum += __shfl_xor_sync(0xffffffff, sum, o);
    if ((tid & 31) == 0) red[tid >> 5] = sum;
    __syncthreads();
    if (tid == 0) {
        float s = 0.f;
#pragma unroll
        for (int i = 0; i < 8; i++) s += red[i];
        bcast = s;
    }
    __syncthreads();
    float mu = bcast * (1.0f / EMBED);

    float var = 0.f;
#pragma unroll
    for (int i = 0; i < 8; i++) {
        float d = v[i] - mu;
        var += d * d;
    }
#pragma unroll
    for (int o = 16; o > 0; o >>= 1) var += __shfl_xor_sync(0xffffffff, var, o);
    if ((tid & 31) == 0) red[tid >> 5] = var;
    __syncthreads();
    if (tid == 0) {
        float s = 0.f;
#pragma unroll
        for (int i = 0; i < 8; i++) s += red[i];
        bcast = s;
    }
    __syncthreads();
    float inv = rsqrtf(bcast * (1.0f / EMBED) + LN_EPS);

#pragma unroll
    for (int i = 0; i < 8; i++) {
        int idx = tid + i * 256;
        out[(size_t)r * EMBED + idx] = (v[i] - mu) * inv * g[idx] + be[idx];
    }
}

// ---------------- launch ----------------------------------------------------
extern "C" void kernel_launch(void* const* d_in, const int* in_sizes, int n_in,
                              void* d_out, int out_size) {
    const float* x  = (const float*)d_in[0];
    const float* Wq = (const float*)d_in[1];
    const float* bq = (const float*)d_in[2];
    const float* Wk = (const float*)d_in[3];
    const float* bk = (const float*)d_in[4];
    const float* Wv = (const float*)d_in[5];
    const float* bv = (const float*)d_in[6];
    const float* Wo = (const float*)d_in[7];
    const float* bo = (const float*)d_in[8];
    const float* g1 = (const float*)d_in[9];
    const float* b1 = (const float*)d_in[10];
    const float* g2 = (const float*)d_in[11];
    const float* b2 = (const float*)d_in[12];
    const float* W1  = (const float*)d_in[13];
    const float* bf1 = (const float*)d_in[14];
    const float* W2  = (const float*)d_in[15];
    const float* bf2 = (const float*)d_in[16];
    float* out = (float*)d_out;

    float *q, *k, *v, *attn, *tmp, *h, *ff;
    cudaGetSymbolAddress((void**)&q, g_q);
    cudaGetSymbolAddress((void**)&k, g_k);
    cudaGetSymbolAddress((void**)&v, g_v);
    cudaGetSymbolAddress((void**)&attn, g_attn);
    cudaGetSymbolAddress((void**)&tmp, g_tmp);
    cudaGetSymbolAddress((void**)&h, g_h);
    cudaGetSymbolAddress((void**)&ff, g_ff);

    __nv_bfloat16 *wqh, *wql, *wkh, *wkl, *wvh, *wvl, *woh, *wol, *w1h, *w1l, *w2h, *w2l;
    cudaGetSymbolAddress((void**)&wqh, g_wq_hi);
    cudaGetSymbolAddress((void**)&wql, g_wq_lo);
    cudaGetSymbolAddress((void**)&wkh, g_wk_hi);
    cudaGetSymbolAddress((void**)&wkl, g_wk_lo);
    cudaGetSymbolAddress((void**)&wvh, g_wv_hi);
    cudaGetSymbolAddress((void**)&wvl, g_wv_lo);
    cudaGetSymbolAddress((void**)&woh, g_wo_hi);
    cudaGetSymbolAddress((void**)&wol, g_wo_lo);
    cudaGetSymbolAddress((void**)&w1h, g_w1_hi);
    cudaGetSymbolAddress((void**)&w1l, g_w1_lo);
    cudaGetSymbolAddress((void**)&w2h, g_w2_hi);
    cudaGetSymbolAddress((void**)&w2l, g_w2_lo);

    const int attn_smem = ATTN_SMEM_FLOATS * sizeof(float);
    cudaFuncSetAttribute(attn_kernel, cudaFuncAttributeMaxDynamicSharedMemorySize, attn_smem);

    dim3 blk(256);

    // ---- weight prep (split + transpose) ----
    split_transpose_kernel<<<dim3(EMBED / 32, EMBED / 32), blk>>>(Wq, wqh, wql, EMBED, EMBED);
    split_transpose_kernel<<<dim3(EMBED / 32, EMBED / 32), blk>>>(Wk, wkh, wkl, EMBED, EMBED);
    split_transpose_kernel<<<dim3(EMBED / 32, EMBED / 32), blk>>>(Wv, wvh, wvl, EMBED, EMBED);
    split_transpose_kernel<<<dim3(EMBED / 32, EMBED / 32), blk>>>(Wo, woh, wol, EMBED, EMBED);
    split_transpose_kernel<<<dim3(EMBED / 32, DFF / 32), blk>>>(W1, w1h, w1l, EMBED, DFF);
    split_transpose_kernel<<<dim3(DFF / 32, EMBED / 32), blk>>>(W2, w2h, w2l, DFF, EMBED);

    dim3 grid_proj(EMBED / 128, MROWS / 128);   // (16, 32)
    dim3 grid_ff1(DFF / 128, MROWS / 128);      // (64, 32)

    // QKV projections
    gemm_tc_kernel<0><<<grid_proj, blk>>>(x, wqh, wql, bq, q, MROWS, EMBED, EMBED);
    gemm_tc_kernel<0><<<grid_proj, blk>>>(x, wkh, wkl, bk, k, MROWS, EMBED, EMBED);
    gemm_tc_kernel<0><<<grid_proj, blk>>>(x, wvh, wvl, bv, v, MROWS, EMBED, EMBED);

    // attention
    attn_kernel<<<dim3(SEQ / QT, 2 * NH), blk, attn_smem>>>(q, k, v, attn);

    // output projection, residual + LN1
    gemm_tc_kernel<0><<<grid_proj, blk>>>(attn, woh, wol, bo, tmp, MROWS, EMBED, EMBED);
    add_ln_kernel<<<MROWS, blk>>>(x, tmp, g1, b1, h);

    // FFN
    gemm_tc_kernel<1><<<grid_ff1, blk>>>(h, w1h, w1l, bf1, ff, MROWS, DFF, EMBED);
    gemm_tc_kernel<0><<<grid_proj, blk>>>(ff, w2h, w2l, bf2, tmp, MROWS, EMBED, DFF);

    // residual + LN2 -> output
    add_ln_kernel<<<MROWS, blk>>>(h, tmp, g2, b2, out);
}